// round 2
// baseline (speedup 1.0000x reference)
#include <cuda_runtime.h>

#define EPS 1e-4f
#define FRAMES 4000
#define T 256
#define E 16                      // elements per thread; 256*16 = 4096 >= 4000
#define PADDED(i) ((i) + ((i) >> 5))
#define SMEM_ELEMS PADDED(4096)   // 4224 floats

__global__ __launch_bounds__(T) void cumnorm_kernel(const float* __restrict__ x,
                                                    float* __restrict__ out) {
    __shared__ float sx[SMEM_ELEMS];
    __shared__ float wsum1[8];
    __shared__ float wsum2[8];

    const long long row = blockIdx.x;
    const float* __restrict__ xr = x + row * (long long)FRAMES;
    float* __restrict__ outr = out + row * (long long)FRAMES;
    const int tid = threadIdx.x;

    // 1) coalesced load into swizzled shared; zero-pad tail [4000, 4096)
    for (int i = tid; i < FRAMES; i += T) sx[PADDED(i)] = xr[i];
    for (int i = FRAMES + tid; i < 4096; i += T) sx[PADDED(i)] = 0.0f;
    __syncthreads();

    // 2) per-thread chunk into registers + local sums
    const int base = tid * E;
    float v[E];
    float s1 = 0.0f, s2 = 0.0f;
#pragma unroll
    for (int i = 0; i < E; i++) {
        float a = sx[PADDED(base + i)];
        v[i] = a;
        s1 += a;
        s2 += a * a;
    }

    // 3) block-wide exclusive scan of (s1, s2)
    const int lane = tid & 31;
    const int wid = tid >> 5;
    float i1 = s1, i2 = s2;
#pragma unroll
    for (int o = 1; o < 32; o <<= 1) {
        float t1 = __shfl_up_sync(0xffffffffu, i1, o);
        float t2 = __shfl_up_sync(0xffffffffu, i2, o);
        if (lane >= o) { i1 += t1; i2 += t2; }
    }
    if (lane == 31) { wsum1[wid] = i1; wsum2[wid] = i2; }
    __syncthreads();

    float w1 = 0.0f, w2 = 0.0f;
#pragma unroll
    for (int w = 0; w < 8; w++) {
        if (w < wid) { w1 += wsum1[w]; w2 += wsum2[w]; }
    }
    // exclusive prefix for this thread's chunk
    float r1 = w1 + (i1 - s1);
    float r2 = w2 + (i2 - s2);

    // 4) sequential causal normalization within the chunk
#pragma unroll
    for (int i = 0; i < E; i++) {
        float a = v[i];
        r1 += a;
        r2 += a * a;
        float inv_cnt = 1.0f / (float)(base + i + 1);
        float mean = r1 * inv_cnt;
        float var = r2 * inv_cnt - mean * mean;
        sx[PADDED(base + i)] = (a - mean) * rsqrtf(var + EPS);
    }
    __syncthreads();

    // 5) coalesced store
    for (int i = tid; i < FRAMES; i += T) outr[i] = sx[PADDED(i)];
}

extern "C" void kernel_launch(void* const* d_in, const int* in_sizes, int n_in,
                              void* d_out, int out_size) {
    const float* x = (const float*)d_in[0];
    float* out = (float*)d_out;
    const int rows = in_sizes[0] / FRAMES;  // 32*512 = 16384
    cumnorm_kernel<<<rows, T>>>(x, out);
}

// round 5
// speedup vs baseline: 2.6448x; 2.6448x over previous
#include <cuda_runtime.h>

#define EPS 1e-4f
#define FRAMES 4000
#define NF4 1000            // 4000 floats = 1000 float4
#define T 256               // threads per CTA; each owns 4 float4 = 16 elements

// XOR swizzle on float4 index: conflict-free for consecutive-index access
// (coalesced load/store phase) AND stride-4 chunk access (4t+j).
__device__ __forceinline__ int swz(int i) { return i ^ ((i >> 3) & 7); }

__global__ __launch_bounds__(T) void cumnorm_kernel(const float4* __restrict__ x,
                                                    float4* __restrict__ out) {
    __shared__ float4 sx[1024];       // 16 KB
    __shared__ float wsum1[8];
    __shared__ float wsum2[8];

    const int tid = threadIdx.x;
    const long long rowbase = (long long)blockIdx.x * NF4;
    const float4* __restrict__ xr = x + rowbase;
    float4* __restrict__ outr = out + rowbase;

    // 1) coalesced vector load into swizzled shared; zero-pad [1000, 1024)
#pragma unroll
    for (int k = 0; k < 4; k++) {
        int i = tid + k * T;
        float4 a = make_float4(0.f, 0.f, 0.f, 0.f);
        if (i < NF4) a = xr[i];
        sx[swz(i)] = a;
    }
    __syncthreads();

    // 2) per-thread contiguous chunk (16 elements = 4 float4) + local sums
    float4 v[4];
    float s1 = 0.f, s2 = 0.f;
#pragma unroll
    for (int j = 0; j < 4; j++) {
        float4 a = sx[swz(4 * tid + j)];
        v[j] = a;
        s1 += a.x + a.y + a.z + a.w;
        s2 = fmaf(a.x, a.x, s2); s2 = fmaf(a.y, a.y, s2);
        s2 = fmaf(a.z, a.z, s2); s2 = fmaf(a.w, a.w, s2);
    }

    // 3) block-wide exclusive scan of (s1, s2)
    const int lane = tid & 31;
    const int wid = tid >> 5;
    float i1 = s1, i2 = s2;
#pragma unroll
    for (int o = 1; o < 32; o <<= 1) {
        float t1 = __shfl_up_sync(0xffffffffu, i1, o);
        float t2 = __shfl_up_sync(0xffffffffu, i2, o);
        if (lane >= o) { i1 += t1; i2 += t2; }
    }
    if (lane == 31) { wsum1[wid] = i1; wsum2[wid] = i2; }
    __syncthreads();

    float w1 = 0.f, w2 = 0.f;
#pragma unroll
    for (int w = 0; w < 8; w++) {
        if (w < wid) { w1 += wsum1[w]; w2 += wsum2[w]; }
    }
    float r1 = w1 + (i1 - s1);   // exclusive prefix sums for this chunk
    float r2 = w2 + (i2 - s2);

    // 4) causal normalization, division-free:
    //    (x - r1/c) / sqrt(r2/c - (r1/c)^2 + eps)
    //  = (c*x - r1) * rsqrt(c*r2 - r1^2 + eps*c^2)
    float c = (float)(16 * tid);
#pragma unroll
    for (int j = 0; j < 4; j++) {
        float4 a = v[j];
        float4 o;
        {
            c += 1.f; r1 += a.x; r2 = fmaf(a.x, a.x, r2);
            float S = fmaf(EPS * c, c, fmaf(c, r2, -r1 * r1));
            o.x = fmaf(c, a.x, -r1) * rsqrtf(S);
        }
        {
            c += 1.f; r1 += a.y; r2 = fmaf(a.y, a.y, r2);
            float S = fmaf(EPS * c, c, fmaf(c, r2, -r1 * r1));
            o.y = fmaf(c, a.y, -r1) * rsqrtf(S);
        }
        {
            c += 1.f; r1 += a.z; r2 = fmaf(a.z, a.z, r2);
            float S = fmaf(EPS * c, c, fmaf(c, r2, -r1 * r1));
            o.z = fmaf(c, a.z, -r1) * rsqrtf(S);
        }
        {
            c += 1.f; r1 += a.w; r2 = fmaf(a.w, a.w, r2);
            float S = fmaf(EPS * c, c, fmaf(c, r2, -r1 * r1));
            o.w = fmaf(c, a.w, -r1) * rsqrtf(S);
        }
        sx[swz(4 * tid + j)] = o;
    }
    __syncthreads();

    // 5) coalesced vector store
#pragma unroll
    for (int k = 0; k < 4; k++) {
        int i = tid + k * T;
        if (i < NF4) outr[i] = sx[swz(i)];
    }
}

extern "C" void kernel_launch(void* const* d_in, const int* in_sizes, int n_in,
                              void* d_out, int out_size) {
    const float4* x = (const float4*)d_in[0];
    float4* out = (float4*)d_out;
    const int rows = in_sizes[0] / FRAMES;   // 32*512 = 16384
    cumnorm_kernel<<<rows, T>>>(x, out);
}